// round 7
// baseline (speedup 1.0000x reference)
#include <cuda_runtime.h>
#include <math.h>
#include <stdint.h>

// ---------------------------------------------------------------------------
// DCRNN encoder, TF32 mma.sync, Chebyshev-collapsed diffusion + LAYER WAVEFRONT.
// T=32, B=32, N=512, D=H=128, K=2 (num_mat=3), L=2.
//
// x1 = S@x ; x2 = (2S^2 - I)@x = M2@x  (M2 precomputed fp32, independent terms)
// Layer wavefront: slot s runs layer0@t=s and layer1@t=s-1 in the SAME batched
// launches (layer1 consumes layer0's output stream via a ping-pong buffer).
// Layer0 x-contributions precomputed for all T in parallel; layer1 does its
// full concat per slot (6 K-segments of 128).
// Layout [N, B, F]: diffusion = A[512,512] @ X[512,4096].
// ---------------------------------------------------------------------------

namespace {
constexpr int TT = 32, BB = 32, NN = 512, HH = 128, LL = 2;
constexpr long NBH  = (long)NN * BB * HH;       // 2,097,152
constexpr long TNBH = (long)TT * NBH;
constexpr long TNBG = (long)TT * NN * BB * 256;
}

// Scratch
__device__ float g_X0[TNBH];
__device__ float g_X1[TNBH];
__device__ float g_X2[TNBH];
__device__ float g_GXg[TNBG];   // layer0 gate x-contrib (+bias)
__device__ float g_GXc[TNBH];   // layer0 cand x-contrib (+bias)
__device__ float g_h0[NBH], g_h1[NBH];
__device__ float g_d1_0[NBH], g_d2_0[NBH];     // diffusion of h0
__device__ float g_d1_1[NBH], g_d2_1[NBH];     // diffusion of h1
__device__ float g_xd1[NBH],  g_xd2[NBH];      // diffusion of layer1 input x
__device__ float g_RH0_0[NBH], g_RHd1_0[NBH], g_RHd2_0[NBH];
__device__ float g_RH0_1[NBH], g_RHd1_1[NBH], g_RHd2_1[NBH];
__device__ float g_U0[NBH], g_U1[NBH];
__device__ float g_o0a[NBH], g_o0b[NBH];       // layer0 output ping-pong
__device__ float g_M2[512 * 512];
__device__ float g_WgT[(long)LL * 256 * 768];  // [L][256][768]
__device__ float g_WcT[(long)LL * 128 * 768];  // [L][128][768]

// ---------------------------------------------------------------------------
__device__ __forceinline__ float tf32r(float x) {
    uint32_t u; asm("cvt.rna.tf32.f32 %0, %1;" : "=r"(u) : "f"(x));
    return __uint_as_float(u);
}
__device__ __forceinline__ void mma_tf32(float* d, const uint32_t* a, const uint32_t* b) {
    asm volatile(
        "mma.sync.aligned.m16n8k8.row.col.f32.tf32.tf32.f32 "
        "{%0,%1,%2,%3}, {%4,%5,%6,%7}, {%8,%9}, {%0,%1,%2,%3};\n"
        : "+f"(d[0]), "+f"(d[1]), "+f"(d[2]), "+f"(d[3])
        : "r"(a[0]), "r"(a[1]), "r"(a[2]), "r"(a[3]), "r"(b[0]), "r"(b[1]));
}

// ---------------------------------------------------------------------------
// M2 = 2*S@S - I, fp32
__global__ void sq_k(const float* __restrict__ S, float* __restrict__ M2) {
    __shared__ float As[32][33];
    __shared__ float Bs[32][33];
    int tx = threadIdx.x, ty = threadIdx.y;
    int row = (blockIdx.y << 5) + ty, col = (blockIdx.x << 5) + tx;
    float acc = 0.f;
    for (int k0 = 0; k0 < 512; k0 += 32) {
        As[ty][tx] = S[(long)row * 512 + k0 + tx];
        Bs[ty][tx] = S[(long)(k0 + ty) * 512 + col];
        __syncthreads();
#pragma unroll
        for (int kk = 0; kk < 32; kk++) acc += As[ty][kk] * Bs[kk][tx];
        __syncthreads();
    }
    M2[(long)row * 512 + col] = 2.f * acc - (row == col ? 1.f : 0.f);
}

// transpose inputs [T,B,N,D] -> [T,N,B,D]
__global__ void transpose_in_k(const float4* __restrict__ in, float4* __restrict__ out) {
    long idx = (long)blockIdx.x * blockDim.x + threadIdx.x;
    int d4 = (int)(idx & 31);
    long rr = idx >> 5;
    int b = (int)(rr & 31); rr >>= 5;
    int n = (int)(rr & 511); rr >>= 9;
    int t = (int)rr;
    out[idx] = in[((((long)t * BB + b) * NN + n) << 5) + d4];
}

// transpose hidden [B,N,H] -> [N,B,H]
__global__ void transpose_h_k(const float4* __restrict__ in, float4* __restrict__ out) {
    long idx = (long)blockIdx.x * blockDim.x + threadIdx.x;
    int d4 = (int)(idx & 31);
    int b  = (int)((idx >> 5) & 31);
    int n  = (int)(idx >> 10);
    out[idx] = in[(((long)b * NN + n) << 5) + d4];
}

// all 4 weight transposes in one kernel
__global__ void transpose_w_all(const float* __restrict__ Wg, const float* __restrict__ Wc,
                                float* __restrict__ WgT, float* __restrict__ WcT) {
    int idx = blockIdx.x * blockDim.x + threadIdx.x;
    const int NG = 2 * 768 * 256;
    const int NCt = 2 * 768 * 128;
    if (idx < NG) {
        int l = idx / (768 * 256), r = idx % (768 * 256);
        int f = r / 256, o = r % 256;
        WgT[(long)l * 256 * 768 + (long)o * 768 + f] = Wg[(long)l * 768 * 256 + (long)f * 256 + o];
    } else if (idx < NG + NCt) {
        int j = idx - NG;
        int l = j / (768 * 128), r = j % (768 * 128);
        int f = r / 128, o = r % 128;
        WcT[(long)l * 128 * 768 + (long)o * 768 + f] = Wc[(long)l * 768 * 128 + (long)f * 128 + o];
    }
}

// ---------------------------------------------------------------------------
// Strided batched diffusion (precompute): z=2*pair+which, C_which[pair]=(which?M2:S)@B[pair]
__global__ __launch_bounds__(256, 2) void gemm_diff2(
    const float* __restrict__ Sa, const float* __restrict__ M2a,
    const float* __restrict__ Bbase, long bStride,
    float* __restrict__ C1, float* __restrict__ C2, long cStride)
{
    constexpr int NC = 4096;
    const int pair = blockIdx.z >> 1, which = blockIdx.z & 1;
    const float* A  = which ? M2a : Sa;
    const float* Bp = Bbase + (long)pair * bStride;
    float* Cp = (which ? C2 : C1) + (long)pair * cStride;

    __shared__ float As[2][16][136];
    __shared__ float Bs[2][16][136];

    const int tid = threadIdx.x;
    const int lane = tid & 31, warp = tid >> 5;
    const int wm0 = (warp & 1) << 6;
    const int wn0 = (warp >> 1) << 5;
    const int r = lane >> 2, c = lane & 3;
    const int m0 = blockIdx.y << 7, n0 = blockIdx.x << 7;
    const int a_row = tid >> 1, a_q = (tid & 1) << 3;
    const int b_row = tid >> 4, b_q = (tid & 15) << 3;

    float acc[4][4][4] = {};
    float4 ra0, ra1, rb0, rb1;

    auto load_regs = [&](int k0) {
        const float* ap = A + (long)(m0 + a_row) * 512 + k0 + a_q;
        ra0 = *(const float4*)(ap); ra1 = *(const float4*)(ap + 4);
        const float* bp = Bp + (long)(k0 + b_row) * NC + n0 + b_q;
        rb0 = *(const float4*)(bp); rb1 = *(const float4*)(bp + 4);
    };
    auto store_smem = [&](int s) {
        As[s][a_q + 0][a_row] = tf32r(ra0.x); As[s][a_q + 1][a_row] = tf32r(ra0.y);
        As[s][a_q + 2][a_row] = tf32r(ra0.z); As[s][a_q + 3][a_row] = tf32r(ra0.w);
        As[s][a_q + 4][a_row] = tf32r(ra1.x); As[s][a_q + 5][a_row] = tf32r(ra1.y);
        As[s][a_q + 6][a_row] = tf32r(ra1.z); As[s][a_q + 7][a_row] = tf32r(ra1.w);
        Bs[s][b_row][b_q + 0] = tf32r(rb0.x); Bs[s][b_row][b_q + 1] = tf32r(rb0.y);
        Bs[s][b_row][b_q + 2] = tf32r(rb0.z); Bs[s][b_row][b_q + 3] = tf32r(rb0.w);
        Bs[s][b_row][b_q + 4] = tf32r(rb1.x); Bs[s][b_row][b_q + 5] = tf32r(rb1.y);
        Bs[s][b_row][b_q + 6] = tf32r(rb1.z); Bs[s][b_row][b_q + 7] = tf32r(rb1.w);
    };

    load_regs(0); store_smem(0); __syncthreads();
    int cur = 0;
    for (int k0 = 0; k0 < 512; k0 += 16) {
        const bool more = (k0 + 16 < 512);
        if (more) load_regs(k0 + 16);
#pragma unroll
        for (int kk = 0; kk < 16; kk += 8) {
            uint32_t af[4][4], bf[4][2];
#pragma unroll
            for (int mi = 0; mi < 4; mi++) {
                int mm = wm0 + mi * 16 + r;
                af[mi][0] = __float_as_uint(As[cur][kk + c][mm]);
                af[mi][1] = __float_as_uint(As[cur][kk + c][mm + 8]);
                af[mi][2] = __float_as_uint(As[cur][kk + c + 4][mm]);
                af[mi][3] = __float_as_uint(As[cur][kk + c + 4][mm + 8]);
            }
#pragma unroll
            for (int ni = 0; ni < 4; ni++) {
                int nn = wn0 + ni * 8 + r;
                bf[ni][0] = __float_as_uint(Bs[cur][kk + c][nn]);
                bf[ni][1] = __float_as_uint(Bs[cur][kk + c + 4][nn]);
            }
#pragma unroll
            for (int mi = 0; mi < 4; mi++)
#pragma unroll
                for (int ni = 0; ni < 4; ni++)
                    mma_tf32(acc[mi][ni], af[mi], bf[ni]);
        }
        if (more) store_smem(cur ^ 1);
        __syncthreads();
        cur ^= 1;
    }
#pragma unroll
    for (int mi = 0; mi < 4; mi++) {
        int row = m0 + wm0 + mi * 16 + r;
#pragma unroll
        for (int ni = 0; ni < 4; ni++) {
            int col = n0 + wn0 + ni * 8 + 2 * c;
            const float* ap = acc[mi][ni];
            long o0 = (long)row * NC + col, o1 = o0 + 8L * NC;
            float2 q0, q1;
            q0.x = ap[0]; q0.y = ap[1]; q1.x = ap[2]; q1.y = ap[3];
            *(float2*)(Cp + o0) = q0;
            *(float2*)(Cp + o1) = q1;
        }
    }
}

// ---------------------------------------------------------------------------
// Slot diffusion: up to 6 independent units (in, out, S-or-M2), grid.z = unit.
__global__ __launch_bounds__(256, 2) void gemm_diff_s(
    const float* __restrict__ Sa, const float* __restrict__ M2a,
    const float* i0, const float* i1, const float* i2,
    const float* i3, const float* i4, const float* i5,
    float* o0p, float* o1p, float* o2p, float* o3p, float* o4p, float* o5p,
    int whichMask)
{
    constexpr int NC = 4096;
    const float* Bp; float* Cp;
    switch (blockIdx.z) {
        case 0: Bp = i0; Cp = o0p; break;
        case 1: Bp = i1; Cp = o1p; break;
        case 2: Bp = i2; Cp = o2p; break;
        case 3: Bp = i3; Cp = o3p; break;
        case 4: Bp = i4; Cp = o4p; break;
        default: Bp = i5; Cp = o5p; break;
    }
    const float* A = ((whichMask >> blockIdx.z) & 1) ? M2a : Sa;

    __shared__ float As[2][16][136];
    __shared__ float Bs[2][16][136];

    const int tid = threadIdx.x;
    const int lane = tid & 31, warp = tid >> 5;
    const int wm0 = (warp & 1) << 6;
    const int wn0 = (warp >> 1) << 5;
    const int r = lane >> 2, c = lane & 3;
    const int m0 = blockIdx.y << 7, n0 = blockIdx.x << 7;
    const int a_row = tid >> 1, a_q = (tid & 1) << 3;
    const int b_row = tid >> 4, b_q = (tid & 15) << 3;

    float acc[4][4][4] = {};
    float4 ra0, ra1, rb0, rb1;

    auto load_regs = [&](int k0) {
        const float* ap = A + (long)(m0 + a_row) * 512 + k0 + a_q;
        ra0 = *(const float4*)(ap); ra1 = *(const float4*)(ap + 4);
        const float* bp = Bp + (long)(k0 + b_row) * NC + n0 + b_q;
        rb0 = *(const float4*)(bp); rb1 = *(const float4*)(bp + 4);
    };
    auto store_smem = [&](int s) {
        As[s][a_q + 0][a_row] = tf32r(ra0.x); As[s][a_q + 1][a_row] = tf32r(ra0.y);
        As[s][a_q + 2][a_row] = tf32r(ra0.z); As[s][a_q + 3][a_row] = tf32r(ra0.w);
        As[s][a_q + 4][a_row] = tf32r(ra1.x); As[s][a_q + 5][a_row] = tf32r(ra1.y);
        As[s][a_q + 6][a_row] = tf32r(ra1.z); As[s][a_q + 7][a_row] = tf32r(ra1.w);
        Bs[s][b_row][b_q + 0] = tf32r(rb0.x); Bs[s][b_row][b_q + 1] = tf32r(rb0.y);
        Bs[s][b_row][b_q + 2] = tf32r(rb0.z); Bs[s][b_row][b_q + 3] = tf32r(rb0.w);
        Bs[s][b_row][b_q + 4] = tf32r(rb1.x); Bs[s][b_row][b_q + 5] = tf32r(rb1.y);
        Bs[s][b_row][b_q + 6] = tf32r(rb1.z); Bs[s][b_row][b_q + 7] = tf32r(rb1.w);
    };

    load_regs(0); store_smem(0); __syncthreads();
    int cur = 0;
    for (int k0 = 0; k0 < 512; k0 += 16) {
        const bool more = (k0 + 16 < 512);
        if (more) load_regs(k0 + 16);
#pragma unroll
        for (int kk = 0; kk < 16; kk += 8) {
            uint32_t af[4][4], bf[4][2];
#pragma unroll
            for (int mi = 0; mi < 4; mi++) {
                int mm = wm0 + mi * 16 + r;
                af[mi][0] = __float_as_uint(As[cur][kk + c][mm]);
                af[mi][1] = __float_as_uint(As[cur][kk + c][mm + 8]);
                af[mi][2] = __float_as_uint(As[cur][kk + c + 4][mm]);
                af[mi][3] = __float_as_uint(As[cur][kk + c + 4][mm + 8]);
            }
#pragma unroll
            for (int ni = 0; ni < 4; ni++) {
                int nn = wn0 + ni * 8 + r;
                bf[ni][0] = __float_as_uint(Bs[cur][kk + c][nn]);
                bf[ni][1] = __float_as_uint(Bs[cur][kk + c + 4][nn]);
            }
#pragma unroll
            for (int mi = 0; mi < 4; mi++)
#pragma unroll
                for (int ni = 0; ni < 4; ni++)
                    mma_tf32(acc[mi][ni], af[mi], bf[ni]);
        }
        if (more) store_smem(cur ^ 1);
        __syncthreads();
        cur ^= 1;
    }
#pragma unroll
    for (int mi = 0; mi < 4; mi++) {
        int row = m0 + wm0 + mi * 16 + r;
#pragma unroll
        for (int ni = 0; ni < 4; ni++) {
            int col = n0 + wn0 + ni * 8 + 2 * c;
            const float* ap = acc[mi][ni];
            long q0o = (long)row * NC + col, q1o = q0o + 8L * NC;
            float2 q0, q1;
            q0.x = ap[0]; q0.y = ap[1]; q1.x = ap[2]; q1.y = ap[3];
            *(float2*)(Cp + q0o) = q0;
            *(float2*)(Cp + q1o) = q1;
        }
    }
}

// ---------------------------------------------------------------------------
// Generalized projection: up to 6 K-segments of 128; grid.z selects arg pack.
struct PJ {
    const float* A0; const float* A1; const float* A2;
    const float* A3; const float* A4; const float* A5;
    int offpack;            // 4 bits per seg: weight col offset / 128
    int nseg;
    const float* WT;        // [O, 768]
    const float* pre;       // optional pre-activation add
    const float* bias;      // optional bias[col]
    float* outC; int nout;  // mode 0
    int mode;               // 0 plain, 1 gates, 2 candidate
    const float* hprev; float* rh0; float* uarr;
    float* hnew; float* o_nbh; float* o_bnh; float* finp; int t;
};

__device__ __forceinline__ const float* segA(const PJ& p, int s) {
    switch (s) {
        case 0: return p.A0; case 1: return p.A1; case 2: return p.A2;
        case 3: return p.A3; case 4: return p.A4; default: return p.A5;
    }
}

__global__ __launch_bounds__(256, 2) void gemm_proj_w(PJ p0, PJ p1) {
    const PJ& p = (blockIdx.z == 0) ? p0 : p1;

    __shared__ float As[2][16][136];
    __shared__ float Bs[2][16][136];

    const int tid = threadIdx.x;
    const int lane = tid & 31, warp = tid >> 5;
    const int wm0 = (warp & 1) << 6;
    const int wn0 = (warp >> 1) << 5;
    const int r = lane >> 2, c = lane & 3;
    const int m0 = blockIdx.y << 7, n0 = blockIdx.x << 7;
    const int a_row = tid >> 1, a_q = (tid & 1) << 3;
    const int b_row = tid >> 1, b_q = (tid & 1) << 3;

    const int KTOT = p.nseg << 7;

    float acc[4][4][4] = {};
    float4 ra0, ra1, rb0, rb1;

    auto load_regs = [&](int k0) {
        int seg = k0 >> 7, within = k0 & 127;
        int off = ((p.offpack >> (seg << 2)) & 15) << 7;
        const float* ap = segA(p, seg) + (long)(m0 + a_row) * 128 + within + a_q;
        ra0 = *(const float4*)(ap); ra1 = *(const float4*)(ap + 4);
        const float* bp = p.WT + (long)(n0 + b_row) * 768 + off + within + b_q;
        rb0 = *(const float4*)(bp); rb1 = *(const float4*)(bp + 4);
    };
    auto store_smem = [&](int s) {
        As[s][a_q + 0][a_row] = tf32r(ra0.x); As[s][a_q + 1][a_row] = tf32r(ra0.y);
        As[s][a_q + 2][a_row] = tf32r(ra0.z); As[s][a_q + 3][a_row] = tf32r(ra0.w);
        As[s][a_q + 4][a_row] = tf32r(ra1.x); As[s][a_q + 5][a_row] = tf32r(ra1.y);
        As[s][a_q + 6][a_row] = tf32r(ra1.z); As[s][a_q + 7][a_row] = tf32r(ra1.w);
        Bs[s][b_q + 0][b_row] = tf32r(rb0.x); Bs[s][b_q + 1][b_row] = tf32r(rb0.y);
        Bs[s][b_q + 2][b_row] = tf32r(rb0.z); Bs[s][b_q + 3][b_row] = tf32r(rb0.w);
        Bs[s][b_q + 4][b_row] = tf32r(rb1.x); Bs[s][b_q + 5][b_row] = tf32r(rb1.y);
        Bs[s][b_q + 6][b_row] = tf32r(rb1.z); Bs[s][b_q + 7][b_row] = tf32r(rb1.w);
    };

    load_regs(0); store_smem(0); __syncthreads();
    int cur = 0;
    for (int k0 = 0; k0 < KTOT; k0 += 16) {
        const bool more = (k0 + 16 < KTOT);
        if (more) load_regs(k0 + 16);
#pragma unroll
        for (int kk = 0; kk < 16; kk += 8) {
            uint32_t af[4][4], bf[4][2];
#pragma unroll
            for (int mi = 0; mi < 4; mi++) {
                int mm = wm0 + mi * 16 + r;
                af[mi][0] = __float_as_uint(As[cur][kk + c][mm]);
                af[mi][1] = __float_as_uint(As[cur][kk + c][mm + 8]);
                af[mi][2] = __float_as_uint(As[cur][kk + c + 4][mm]);
                af[mi][3] = __float_as_uint(As[cur][kk + c + 4][mm + 8]);
            }
#pragma unroll
            for (int ni = 0; ni < 4; ni++) {
                int nn = wn0 + ni * 8 + r;
                bf[ni][0] = __float_as_uint(Bs[cur][kk + c][nn]);
                bf[ni][1] = __float_as_uint(Bs[cur][kk + c + 4][nn]);
            }
#pragma unroll
            for (int mi = 0; mi < 4; mi++)
#pragma unroll
                for (int ni = 0; ni < 4; ni++)
                    mma_tf32(acc[mi][ni], af[mi], bf[ni]);
        }
        if (more) store_smem(cur ^ 1);
        __syncthreads();
        cur ^= 1;
    }

#pragma unroll
    for (int mi = 0; mi < 4; mi++) {
#pragma unroll
        for (int ni = 0; ni < 4; ni++) {
            const float* ap = acc[mi][ni];
#pragma unroll
            for (int half = 0; half < 2; half++) {
                int row = m0 + wm0 + mi * 16 + r + half * 8;
                float v0 = ap[half * 2 + 0];
                float v1 = ap[half * 2 + 1];
                int col = n0 + wn0 + ni * 8 + 2 * c;
                if (p.mode == 0) {
                    if (p.bias) { v0 += p.bias[col]; v1 += p.bias[col + 1]; }
                    float2 o; o.x = v0; o.y = v1;
                    *(float2*)(p.outC + (long)row * p.nout + col) = o;
                } else if (p.mode == 1) {
                    if (p.pre) {
                        const float* pp = p.pre + (long)row * 256 + col;
                        v0 += pp[0]; v1 += pp[1];
                    }
                    if (p.bias) { v0 += p.bias[col]; v1 += p.bias[col + 1]; }
                    float g0 = 1.f / (1.f + __expf(-v0));
                    float g1 = 1.f / (1.f + __expf(-v1));
                    if (col < 128) {
                        long o = (long)row * 128 + col;
                        float2 h = *(const float2*)(p.hprev + o);
                        float2 out; out.x = g0 * h.x; out.y = g1 * h.y;
                        *(float2*)(p.rh0 + o) = out;
                    } else {
                        long o = (long)row * 128 + (col - 128);
                        float2 out; out.x = g0; out.y = g1;
                        *(float2*)(p.uarr + o) = out;
                    }
                } else {
                    long o = (long)row * 128 + col;
                    if (p.pre) { v0 += p.pre[o]; v1 += p.pre[o + 1]; }
                    if (p.bias) { v0 += p.bias[col]; v1 += p.bias[col + 1]; }
                    float c0 = tanhf(v0), c1 = tanhf(v1);
                    float2 uu = *(const float2*)(p.uarr + o);
                    float2 hh = *(const float2*)(p.hprev + o);
                    float2 out;
                    out.x = uu.x * hh.x + (1.f - uu.x) * c0;
                    out.y = uu.y * hh.y + (1.f - uu.y) * c1;
                    *(float2*)(p.hnew + o) = out;
                    if (p.o_nbh) *(float2*)(p.o_nbh + o) = out;
                    int nn2 = row >> 5, bb2 = row & 31;
                    if (p.o_bnh)
                        *(float2*)(p.o_bnh + ((((long)p.t * BB + bb2) * NN + nn2) * HH + col)) = out;
                    if (p.finp)
                        *(float2*)(p.finp + (((long)bb2 * NN + nn2) * HH + col)) = out;
                }
            }
        }
    }
}

// ---------------------------------------------------------------------------
extern "C" void kernel_launch(void* const* d_in, const int* in_sizes, int n_in,
                              void* d_out, int out_size) {
    (void)in_sizes; (void)n_in; (void)out_size;
    const float* inputs = (const float*)d_in[0];
    const float* ih     = (const float*)d_in[1];
    const float* S      = (const float*)d_in[2];
    const float* Wg     = (const float*)d_in[3];
    const float* bg     = (const float*)d_in[4];
    const float* Wc     = (const float*)d_in[5];
    const float* bc     = (const float*)d_in[6];
    float* fin    = (float*)d_out;                  // [L,B,N,H]
    float* outcur = fin + (long)LL * BB * NN * HH;  // [T,B,N,H]

    float *pX0, *pX1, *pX2, *pGXg, *pGXc;
    float *ph0, *ph1, *pd1_0, *pd2_0, *pd1_1, *pd2_1, *pxd1, *pxd2;
    float *pR0_0, *pR1_0, *pR2_0, *pR0_1, *pR1_1, *pR2_1;
    float *pU0, *pU1, *po0a, *po0b, *pM2, *pWgT, *pWcT;
    cudaGetSymbolAddress((void**)&pX0, g_X0);
    cudaGetSymbolAddress((void**)&pX1, g_X1);
    cudaGetSymbolAddress((void**)&pX2, g_X2);
    cudaGetSymbolAddress((void**)&pGXg, g_GXg);
    cudaGetSymbolAddress((void**)&pGXc, g_GXc);
    cudaGetSymbolAddress((void**)&ph0, g_h0);
    cudaGetSymbolAddress((void**)&ph1, g_h1);
    cudaGetSymbolAddress((void**)&pd1_0, g_d1_0);
    cudaGetSymbolAddress((void**)&pd2_0, g_d2_0);
    cudaGetSymbolAddress((void**)&pd1_1, g_d1_1);
    cudaGetSymbolAddress((void**)&pd2_1, g_d2_1);
    cudaGetSymbolAddress((void**)&pxd1, g_xd1);
    cudaGetSymbolAddress((void**)&pxd2, g_xd2);
    cudaGetSymbolAddress((void**)&pR0_0, g_RH0_0);
    cudaGetSymbolAddress((void**)&pR1_0, g_RHd1_0);
    cudaGetSymbolAddress((void**)&pR2_0, g_RHd2_0);
    cudaGetSymbolAddress((void**)&pR0_1, g_RH0_1);
    cudaGetSymbolAddress((void**)&pR1_1, g_RHd1_1);
    cudaGetSymbolAddress((void**)&pR2_1, g_RHd2_1);
    cudaGetSymbolAddress((void**)&pU0, g_U0);
    cudaGetSymbolAddress((void**)&pU1, g_U1);
    cudaGetSymbolAddress((void**)&po0a, g_o0a);
    cudaGetSymbolAddress((void**)&po0b, g_o0b);
    cudaGetSymbolAddress((void**)&pM2, g_M2);
    cudaGetSymbolAddress((void**)&pWgT, g_WgT);
    cudaGetSymbolAddress((void**)&pWcT, g_WcT);
    float* out0[2] = {po0a, po0b};

    // ---- setup ----
    sq_k<<<dim3(16, 16), dim3(32, 32)>>>(S, pM2);
    transpose_in_k<<<65536, 256>>>((const float4*)inputs, (float4*)pX0);
    transpose_w_all<<<2304, 256>>>(Wg, Wc, pWgT, pWcT);
    transpose_h_k<<<2048, 256>>>((const float4*)ih, (float4*)ph0);
    transpose_h_k<<<2048, 256>>>((const float4*)(ih + NBH), (float4*)ph1);

    // ---- layer0 x precompute (all T in parallel) ----
    gemm_diff2<<<dim3(32, 4, 2 * TT), 256>>>(S, pM2, pX0, NBH, pX1, pX2, NBH);

    PJ pz = {};  // zero pack for unused z slot
    {
        PJ pg = {};
        pg.A0 = pX0; pg.A1 = pX1; pg.A2 = pX2;
        pg.offpack = 0x420; pg.nseg = 3; pg.WT = pWgT;
        pg.bias = bg; pg.outC = pGXg; pg.nout = 256; pg.mode = 0;
        gemm_proj_w<<<dim3(2, 4096, 1), 256>>>(pg, pz);
        PJ pc = {};
        pc.A0 = pX0; pc.A1 = pX1; pc.A2 = pX2;
        pc.offpack = 0x420; pc.nseg = 3; pc.WT = pWcT;
        pc.bias = bc; pc.outC = pGXc; pc.nout = 128; pc.mode = 0;
        gemm_proj_w<<<dim3(1, 4096, 1), 256>>>(pc, pz);
    }

    const float* wgt1 = pWgT + (long)256 * 768;
    const float* wct1 = pWcT + (long)128 * 768;

    // ---- wavefront: slot s = layer0@t=s (s<TT) + layer1@t=s-1 (s>=1) ----
    for (int s = 0; s <= TT; s++) {
        const bool l0 = (s < TT), l1 = (s > 0);
        const int t0 = s, t1 = s - 1;
        const float* x1 = l1 ? out0[(s - 1) & 1] : nullptr;
        float* o0w = out0[s & 1];

        // Phase 1: diffusion of h (both layers) + layer1 input x
        {
            const float* iu[6] = {}; float* ou[6] = {}; int mask = 0, nz = 0;
            if (l0) {
                iu[nz] = ph0; ou[nz] = pd1_0; nz++;                    // S
                iu[nz] = ph0; ou[nz] = pd2_0; mask |= 1 << nz; nz++;   // M2
            }
            if (l1) {
                iu[nz] = ph1; ou[nz] = pd1_1; nz++;
                iu[nz] = ph1; ou[nz] = pd2_1; mask |= 1 << nz; nz++;
                iu[nz] = x1;  ou[nz] = pxd1;  nz++;
                iu[nz] = x1;  ou[nz] = pxd2;  mask |= 1 << nz; nz++;
            }
            gemm_diff_s<<<dim3(32, 4, nz), 256>>>(S, pM2,
                iu[0], iu[1], iu[2], iu[3], iu[4], iu[5],
                ou[0], ou[1], ou[2], ou[3], ou[4], ou[5], mask);
        }

        // Phase 2: gates
        {
            PJ a = {}, b = {}; int nz = 0;
            if (l0) {
                PJ& p = (nz == 0) ? a : b;
                p.A0 = ph0; p.A1 = pd1_0; p.A2 = pd2_0;
                p.offpack = 0x531; p.nseg = 3; p.WT = pWgT;
                p.pre = pGXg + (long)t0 * NN * BB * 256; p.mode = 1;
                p.hprev = ph0; p.rh0 = pR0_0; p.uarr = pU0; nz++;
            }
            if (l1) {
                PJ& p = (nz == 0) ? a : b;
                p.A0 = x1; p.A1 = pxd1; p.A2 = pxd2;
                p.A3 = ph1; p.A4 = pd1_1; p.A5 = pd2_1;
                p.offpack = 0x531420; p.nseg = 6; p.WT = wgt1;
                p.bias = bg + 256; p.mode = 1;
                p.hprev = ph1; p.rh0 = pR0_1; p.uarr = pU1; nz++;
            }
            gemm_proj_w<<<dim3(2, 128, nz), 256>>>(a, nz > 1 ? b : pz);
        }

        // Phase 3: diffusion of r*h
        {
            const float* iu[6] = {}; float* ou[6] = {}; int mask = 0, nz = 0;
            if (l0) {
                iu[nz] = pR0_0; ou[nz] = pR1_0; nz++;
                iu[nz] = pR0_0; ou[nz] = pR2_0; mask |= 1 << nz; nz++;
            }
            if (l1) {
                iu[nz] = pR0_1; ou[nz] = pR1_1; nz++;
                iu[nz] = pR0_1; ou[nz] = pR2_1; mask |= 1 << nz; nz++;
            }
            gemm_diff_s<<<dim3(32, 4, nz), 256>>>(S, pM2,
                iu[0], iu[1], iu[2], iu[3], iu[4], iu[5],
                ou[0], ou[1], ou[2], ou[3], ou[4], ou[5], mask);
        }

        // Phase 4: candidate + GRU update + outputs
        {
            PJ a = {}, b = {}; int nz = 0;
            if (l0) {
                PJ& p = (nz == 0) ? a : b;
                p.A0 = pR0_0; p.A1 = pR1_0; p.A2 = pR2_0;
                p.offpack = 0x531; p.nseg = 3; p.WT = pWcT;
                p.pre = pGXc + (long)t0 * NN * BB * 128; p.mode = 2;
                p.hprev = ph0; p.uarr = pU0; p.hnew = ph0;
                p.o_nbh = o0w;
                p.finp = (t0 == TT - 1) ? fin : nullptr;
                p.t = t0; nz++;
            }
            if (l1) {
                PJ& p = (nz == 0) ? a : b;
                p.A0 = x1; p.A1 = pxd1; p.A2 = pxd2;
                p.A3 = pR0_1; p.A4 = pR1_1; p.A5 = pR2_1;
                p.offpack = 0x531420; p.nseg = 6; p.WT = wct1;
                p.bias = bc + 128; p.mode = 2;
                p.hprev = ph1; p.uarr = pU1; p.hnew = ph1;
                p.o_bnh = outcur;
                p.finp = (t1 == TT - 1) ? (fin + NBH) : nullptr;
                p.t = t1; nz++;
            }
            gemm_proj_w<<<dim3(1, 128, nz), 256>>>(a, nz > 1 ? b : pz);
        }
    }
}

// round 9
// speedup vs baseline: 1.6240x; 1.6240x over previous
#include <cuda_runtime.h>
#include <math.h>
#include <stdint.h>

// ---------------------------------------------------------------------------
// DCRNN encoder, TF32 mma.sync, Chebyshev-collapsed diffusion.
// Layer-sequential structure (round-3, known good), with bank-conflict-free
// smem staging in the GEMMs:
//   A tile stored [m][k] pitch 20, staged via STS.128 (was 8-way-free already
//   on reads; stores now vectorized, 2-way worst case).
//   B tile (activations) staged float4-granular -> conflict-free STS.128
//   (was 8-way conflicted scalar stores).
// x1 = S@x ; x2 = (2S^2 - I)@x = M2@x (M2 precomputed fp32).
// Layout [N, B, F]: diffusion = A[512,512] @ X[512,4096].
// ---------------------------------------------------------------------------

namespace {
constexpr int TT = 32, BB = 32, NN = 512, HH = 128, LL = 2;
constexpr long NBH  = (long)NN * BB * HH;       // 2,097,152
constexpr long TNBH = (long)TT * NBH;
constexpr long TNBG = (long)TT * NN * BB * 256;
}

// Scratch
__device__ float g_X0[TNBH];
__device__ float g_Xn[TNBH];
__device__ float g_X1[TNBH];
__device__ float g_X2[TNBH];
__device__ float g_GXg[TNBG];
__device__ float g_GXc[TNBH];
__device__ float g_H0[NBH];
__device__ float g_H1[NBH];
__device__ float g_H2[NBH];
__device__ float g_RH0[NBH];
__device__ float g_RH1[NBH];
__device__ float g_RH2[NBH];
__device__ float g_U[NBH];
__device__ float g_M2[512 * 512];
__device__ float g_WgT[(long)LL * 256 * 768];   // [L][256][768]
__device__ float g_WcT[(long)LL * 128 * 768];   // [L][128][768]

// ---------------------------------------------------------------------------
__device__ __forceinline__ float tf32r(float x) {
    uint32_t u; asm("cvt.rna.tf32.f32 %0, %1;" : "=r"(u) : "f"(x));
    return __uint_as_float(u);
}
__device__ __forceinline__ void mma_tf32(float* d, const uint32_t* a, const uint32_t* b) {
    asm volatile(
        "mma.sync.aligned.m16n8k8.row.col.f32.tf32.tf32.f32 "
        "{%0,%1,%2,%3}, {%4,%5,%6,%7}, {%8,%9}, {%0,%1,%2,%3};\n"
        : "+f"(d[0]), "+f"(d[1]), "+f"(d[2]), "+f"(d[3])
        : "r"(a[0]), "r"(a[1]), "r"(a[2]), "r"(a[3]), "r"(b[0]), "r"(b[1]));
}
__device__ __forceinline__ float4 tf4(float4 v) {
    return make_float4(tf32r(v.x), tf32r(v.y), tf32r(v.z), tf32r(v.w));
}

// ---------------------------------------------------------------------------
// M2 = 2*S@S - I, fp32
__global__ void sq_k(const float* __restrict__ S, float* __restrict__ M2) {
    __shared__ float As[32][33];
    __shared__ float Bs[32][33];
    int tx = threadIdx.x, ty = threadIdx.y;
    int row = (blockIdx.y << 5) + ty, col = (blockIdx.x << 5) + tx;
    float acc = 0.f;
    for (int k0 = 0; k0 < 512; k0 += 32) {
        As[ty][tx] = S[(long)row * 512 + k0 + tx];
        Bs[ty][tx] = S[(long)(k0 + ty) * 512 + col];
        __syncthreads();
#pragma unroll
        for (int kk = 0; kk < 32; kk++) acc += As[ty][kk] * Bs[kk][tx];
        __syncthreads();
    }
    M2[(long)row * 512 + col] = 2.f * acc - (row == col ? 1.f : 0.f);
}

// transpose inputs [T,B,N,D] -> [T,N,B,D]
__global__ void transpose_in_k(const float4* __restrict__ in, float4* __restrict__ out) {
    long idx = (long)blockIdx.x * blockDim.x + threadIdx.x;
    int d4 = (int)(idx & 31);
    long rr = idx >> 5;
    int b = (int)(rr & 31); rr >>= 5;
    int n = (int)(rr & 511); rr >>= 9;
    int t = (int)rr;
    out[idx] = in[((((long)t * BB + b) * NN + n) << 5) + d4];
}

// transpose hidden [B,N,H] -> [N,B,H]
__global__ void transpose_h_k(const float4* __restrict__ in, float4* __restrict__ out) {
    long idx = (long)blockIdx.x * blockDim.x + threadIdx.x;
    int d4 = (int)(idx & 31);
    int b  = (int)((idx >> 5) & 31);
    int n  = (int)(idx >> 10);
    out[idx] = in[(((long)b * NN + n) << 5) + d4];
}

// all 4 weight transposes in one kernel
__global__ void transpose_w_all(const float* __restrict__ Wg, const float* __restrict__ Wc,
                                float* __restrict__ WgT, float* __restrict__ WcT) {
    int idx = blockIdx.x * blockDim.x + threadIdx.x;
    const int NG = 2 * 768 * 256;
    const int NCt = 2 * 768 * 128;
    if (idx < NG) {
        int l = idx / (768 * 256), r = idx % (768 * 256);
        int f = r / 256, o = r % 256;
        WgT[(long)l * 256 * 768 + (long)o * 768 + f] = Wg[(long)l * 768 * 256 + (long)f * 256 + o];
    } else if (idx < NG + NCt) {
        int j = idx - NG;
        int l = j / (768 * 128), r = j % (768 * 128);
        int f = r / 128, o = r % 128;
        WcT[(long)l * 128 * 768 + (long)o * 768 + f] = Wc[(long)l * 768 * 128 + (long)f * 128 + o];
    }
}

// ---------------------------------------------------------------------------
// Batched diffusion GEMM (TF32): z = 2*pair + which:
//   C_which[pair] = (which ? M2 : S) @ B[pair]     B: [512, 4096]
// CTA tile 128x128x16, double-buffered; conflict-free staging.
__global__ __launch_bounds__(256, 2) void gemm_diff2(
    const float* __restrict__ Sa, const float* __restrict__ M2a,
    const float* __restrict__ Bbase, long bStride,
    float* __restrict__ C1, float* __restrict__ C2, long cStride)
{
    constexpr int NC = 4096;
    const int pair = blockIdx.z >> 1, which = blockIdx.z & 1;
    const float* A  = which ? M2a : Sa;
    const float* Bp = Bbase + (long)pair * bStride;
    float* Cp = (which ? C2 : C1) + (long)pair * cStride;

    __shared__ float As[2][128][20];   // [stage][m][k] pitch 20
    __shared__ float Bs[2][16][136];   // [stage][k][n]

    const int tid = threadIdx.x;
    const int lane = tid & 31, warp = tid >> 5;
    const int wm0 = (warp & 1) << 6;
    const int wn0 = (warp >> 1) << 5;
    const int r = lane >> 2, c = lane & 3;
    const int m0 = blockIdx.y << 7, n0 = blockIdx.x << 7;

    const int a_row = tid >> 1;            // m 0..127
    const int a_q   = (tid & 1) << 3;      // k 0 or 8
    const int b_k   = tid >> 4;            // k 0..15
    const int b_n4  = (tid & 15) << 2;     // n 0..60 step 4

    float acc[4][4][4] = {};
    float4 ra0, ra1, rb0, rb1;

    auto load_regs = [&](int k0) {
        const float* ap = A + (long)(m0 + a_row) * 512 + k0 + a_q;
        ra0 = *(const float4*)(ap);
        ra1 = *(const float4*)(ap + 4);
        const float* bp = Bp + (long)(k0 + b_k) * NC + n0 + b_n4;
        rb0 = *(const float4*)(bp);
        rb1 = *(const float4*)(bp + 64);
    };
    auto store_smem = [&](int s) {
        *(float4*)&As[s][a_row][a_q]     = tf4(ra0);
        *(float4*)&As[s][a_row][a_q + 4] = tf4(ra1);
        *(float4*)&Bs[s][b_k][b_n4]      = tf4(rb0);
        *(float4*)&Bs[s][b_k][b_n4 + 64] = tf4(rb1);
    };

    load_regs(0); store_smem(0); __syncthreads();
    int cur = 0;
    for (int k0 = 0; k0 < 512; k0 += 16) {
        const bool more = (k0 + 16 < 512);
        if (more) load_regs(k0 + 16);
#pragma unroll
        for (int kk = 0; kk < 16; kk += 8) {
            uint32_t af[4][4], bf[4][2];
#pragma unroll
            for (int mi = 0; mi < 4; mi++) {
                int mm = wm0 + mi * 16 + r;
                af[mi][0] = __float_as_uint(As[cur][mm][kk + c]);
                af[mi][1] = __float_as_uint(As[cur][mm + 8][kk + c]);
                af[mi][2] = __float_as_uint(As[cur][mm][kk + c + 4]);
                af[mi][3] = __float_as_uint(As[cur][mm + 8][kk + c + 4]);
            }
#pragma unroll
            for (int ni = 0; ni < 4; ni++) {
                int nn = wn0 + ni * 8 + r;
                bf[ni][0] = __float_as_uint(Bs[cur][kk + c][nn]);
                bf[ni][1] = __float_as_uint(Bs[cur][kk + c + 4][nn]);
            }
#pragma unroll
            for (int mi = 0; mi < 4; mi++)
#pragma unroll
                for (int ni = 0; ni < 4; ni++)
                    mma_tf32(acc[mi][ni], af[mi], bf[ni]);
        }
        if (more) store_smem(cur ^ 1);
        __syncthreads();
        cur ^= 1;
    }
#pragma unroll
    for (int mi = 0; mi < 4; mi++) {
        int row = m0 + wm0 + mi * 16 + r;
#pragma unroll
        for (int ni = 0; ni < 4; ni++) {
            int col = n0 + wn0 + ni * 8 + 2 * c;
            const float* ap = acc[mi][ni];
            long o0 = (long)row * NC + col, o1 = o0 + 8L * NC;
            float2 q0, q1;
            q0.x = ap[0]; q0.y = ap[1]; q1.x = ap[2]; q1.y = ap[3];
            *(float2*)(Cp + o0) = q0;
            *(float2*)(Cp + o1) = q1;
        }
    }
}

// ---------------------------------------------------------------------------
// Projection GEMM (TF32): D = f( sum_seg A_seg @ WT_seg^T + pre + bias )
// A segs: [M,128]. WT: [O,768] row-major; seg s uses cols s*256+xh_off+0..127.
// modes: 0 plain(+bias)->outC; 1 gates; 2 candidate + GRU update + scatter.
__global__ __launch_bounds__(256, 2) void gemm_proj_t(
    const float* __restrict__ A0, const float* __restrict__ A1, const float* __restrict__ A2,
    const float* __restrict__ WT, int xh_off, int nout,
    const float* __restrict__ pre, const float* __restrict__ bias,
    float* __restrict__ outC, int mode,
    const float* __restrict__ h0c, float* __restrict__ rh0, float* __restrict__ uarr,
    float* __restrict__ h0w, float* __restrict__ out_nbh, float* __restrict__ out_bnh,
    float* __restrict__ finp, int t)
{
    __shared__ float As[2][128][20];   // [stage][m][k]
    __shared__ float Bs[2][16][136];   // [stage][k][n]

    const int tid = threadIdx.x;
    const int lane = tid & 31, warp = tid >> 5;
    const int wm0 = (warp & 1) << 6;
    const int wn0 = (warp >> 1) << 5;
    const int r = lane >> 2, c = lane & 3;
    const int m0 = blockIdx.y << 7, n0 = blockIdx.x << 7;

    const int a_row = tid >> 1;            // m
    const int a_q   = (tid & 1) << 3;      // k 0/8
    const int b_row = tid >> 1;            // n = WT row
    const int b_q   = (tid & 1) << 3;      // k 0/8

    const float* Aseg[3] = {A0, A1, A2};

    float acc[4][4][4] = {};
    float4 ra0, ra1, rb0, rb1;

    auto load_regs = [&](int k0) {
        int seg = k0 >> 7, within = k0 & 127;
        const float* ap = Aseg[seg] + (long)(m0 + a_row) * 128 + within + a_q;
        ra0 = *(const float4*)(ap);
        ra1 = *(const float4*)(ap + 4);
        const float* bp = WT + (long)(n0 + b_row) * 768 + seg * 256 + xh_off + within + b_q;
        rb0 = *(const float4*)(bp);
        rb1 = *(const float4*)(bp + 4);
    };
    auto store_smem = [&](int s) {
        *(float4*)&As[s][a_row][a_q]     = tf4(ra0);
        *(float4*)&As[s][a_row][a_q + 4] = tf4(ra1);
        Bs[s][b_q + 0][b_row] = tf32r(rb0.x); Bs[s][b_q + 1][b_row] = tf32r(rb0.y);
        Bs[s][b_q + 2][b_row] = tf32r(rb0.z); Bs[s][b_q + 3][b_row] = tf32r(rb0.w);
        Bs[s][b_q + 4][b_row] = tf32r(rb1.x); Bs[s][b_q + 5][b_row] = tf32r(rb1.y);
        Bs[s][b_q + 6][b_row] = tf32r(rb1.z); Bs[s][b_q + 7][b_row] = tf32r(rb1.w);
    };

    load_regs(0); store_smem(0); __syncthreads();
    int cur = 0;
    for (int k0 = 0; k0 < 384; k0 += 16) {
        const bool more = (k0 + 16 < 384);
        if (more) load_regs(k0 + 16);
#pragma unroll
        for (int kk = 0; kk < 16; kk += 8) {
            uint32_t af[4][4], bf[4][2];
#pragma unroll
            for (int mi = 0; mi < 4; mi++) {
                int mm = wm0 + mi * 16 + r;
                af[mi][0] = __float_as_uint(As[cur][mm][kk + c]);
                af[mi][1] = __float_as_uint(As[cur][mm + 8][kk + c]);
                af[mi][2] = __float_as_uint(As[cur][mm][kk + c + 4]);
                af[mi][3] = __float_as_uint(As[cur][mm + 8][kk + c + 4]);
            }
#pragma unroll
            for (int ni = 0; ni < 4; ni++) {
                int nn = wn0 + ni * 8 + r;
                bf[ni][0] = __float_as_uint(Bs[cur][kk + c][nn]);
                bf[ni][1] = __float_as_uint(Bs[cur][kk + c + 4][nn]);
            }
#pragma unroll
            for (int mi = 0; mi < 4; mi++)
#pragma unroll
                for (int ni = 0; ni < 4; ni++)
                    mma_tf32(acc[mi][ni], af[mi], bf[ni]);
        }
        if (more) store_smem(cur ^ 1);
        __syncthreads();
        cur ^= 1;
    }

#pragma unroll
    for (int mi = 0; mi < 4; mi++) {
#pragma unroll
        for (int ni = 0; ni < 4; ni++) {
            const float* ap = acc[mi][ni];
#pragma unroll
            for (int half = 0; half < 2; half++) {
                int row = m0 + wm0 + mi * 16 + r + half * 8;
                float v0 = ap[half * 2 + 0];
                float v1 = ap[half * 2 + 1];
                int col = n0 + wn0 + ni * 8 + 2 * c;
                if (mode == 0) {
                    if (bias) { v0 += bias[col]; v1 += bias[col + 1]; }
                    float2 o; o.x = v0; o.y = v1;
                    *(float2*)(outC + (long)row * nout + col) = o;
                } else if (mode == 1) {
                    const float* pp = pre + (long)row * 256 + col;
                    v0 += pp[0]; v1 += pp[1];
                    float g0 = 1.f / (1.f + __expf(-v0));
                    float g1 = 1.f / (1.f + __expf(-v1));
                    if (col < 128) {
                        long o = (long)row * 128 + col;
                        float2 h = *(const float2*)(h0c + o);
                        float2 out; out.x = g0 * h.x; out.y = g1 * h.y;
                        *(float2*)(rh0 + o) = out;
                    } else {
                        long o = (long)row * 128 + (col - 128);
                        float2 out; out.x = g0; out.y = g1;
                        *(float2*)(uarr + o) = out;
                    }
                } else {
                    long o = (long)row * 128 + col;
                    const float* pp = pre + o;
                    v0 += pp[0]; v1 += pp[1];
                    float c0 = tanhf(v0), c1 = tanhf(v1);
                    float2 uu = *(const float2*)(uarr + o);
                    float2 hh = *(const float2*)(h0c + o);
                    float hn0 = uu.x * hh.x + (1.f - uu.x) * c0;
                    float hn1 = uu.y * hh.y + (1.f - uu.y) * c1;
                    float2 out; out.x = hn0; out.y = hn1;
                    *(float2*)(h0w + o) = out;
                    if (out_nbh) *(float2*)(out_nbh + o) = out;
                    int nn2 = row >> 5, bb2 = row & 31;
                    if (out_bnh)
                        *(float2*)(out_bnh + ((((long)t * BB + bb2) * NN + nn2) * HH + col)) = out;
                    if (finp)
                        *(float2*)(finp + (((long)bb2 * NN + nn2) * HH + col)) = out;
                }
            }
        }
    }
}

// ---------------------------------------------------------------------------
extern "C" void kernel_launch(void* const* d_in, const int* in_sizes, int n_in,
                              void* d_out, int out_size) {
    (void)in_sizes; (void)n_in; (void)out_size;
    const float* inputs = (const float*)d_in[0];
    const float* ih     = (const float*)d_in[1];
    const float* S      = (const float*)d_in[2];
    const float* Wg     = (const float*)d_in[3];
    const float* bg     = (const float*)d_in[4];
    const float* Wc     = (const float*)d_in[5];
    const float* bc     = (const float*)d_in[6];
    float* fin    = (float*)d_out;
    float* outcur = fin + (long)LL * BB * NN * HH;

    float *pX0, *pXn, *pX1, *pX2, *pGXg, *pGXc;
    float *pH0, *pH1, *pH2, *pRH0, *pRH1, *pRH2, *pU, *pM2, *pWgT, *pWcT;
    cudaGetSymbolAddress((void**)&pX0, g_X0);
    cudaGetSymbolAddress((void**)&pXn, g_Xn);
    cudaGetSymbolAddress((void**)&pX1, g_X1);
    cudaGetSymbolAddress((void**)&pX2, g_X2);
    cudaGetSymbolAddress((void**)&pGXg, g_GXg);
    cudaGetSymbolAddress((void**)&pGXc, g_GXc);
    cudaGetSymbolAddress((void**)&pH0, g_H0);
    cudaGetSymbolAddress((void**)&pH1, g_H1);
    cudaGetSymbolAddress((void**)&pH2, g_H2);
    cudaGetSymbolAddress((void**)&pRH0, g_RH0);
    cudaGetSymbolAddress((void**)&pRH1, g_RH1);
    cudaGetSymbolAddress((void**)&pRH2, g_RH2);
    cudaGetSymbolAddress((void**)&pU, g_U);
    cudaGetSymbolAddress((void**)&pM2, g_M2);
    cudaGetSymbolAddress((void**)&pWgT, g_WgT);
    cudaGetSymbolAddress((void**)&pWcT, g_WcT);

    // One-time prep
    sq_k<<<dim3(16, 16), dim3(32, 32)>>>(S, pM2);
    transpose_in_k<<<65536, 256>>>((const float4*)inputs, (float4*)pX0);
    transpose_w_all<<<2304, 256>>>(Wg, Wc, pWgT, pWcT);

    for (int l = 0; l < LL; l++) {
        const float* Xin = (l == 0) ? pX0 : pXn;
        const float* wgt = pWgT + (long)l * 256 * 768;
        const float* wct = pWcT + (long)l * 128 * 768;

        // --- parallel precompute of x-contributions (all T, both diffusion terms) ---
        gemm_diff2<<<dim3(32, 4, 2 * TT), 256>>>(S, pM2, Xin, NBH, pX1, pX2, NBH);
        gemm_proj_t<<<dim3(2, 4096), 256>>>(Xin, pX1, pX2, wgt, 0, 256,
            nullptr, bg + l * 256, pGXg, 0,
            nullptr, nullptr, nullptr, nullptr, nullptr, nullptr, nullptr, 0);
        gemm_proj_t<<<dim3(1, 4096), 256>>>(Xin, pX1, pX2, wct, 0, 128,
            nullptr, bc + l * 128, pGXc, 0,
            nullptr, nullptr, nullptr, nullptr, nullptr, nullptr, nullptr, 0);

        transpose_h_k<<<2048, 256>>>((const float4*)(ih + (long)l * BB * NN * HH), (float4*)pH0);

        // --- sequential recurrence: 4 dependent kernels per step ---
        for (int t = 0; t < TT; t++) {
            gemm_diff2<<<dim3(32, 4, 2), 256>>>(S, pM2, pH0, 0, pH1, pH2, 0);
            gemm_proj_t<<<dim3(2, 128), 256>>>(pH0, pH1, pH2, wgt, 128, 256,
                pGXg + (long)t * NN * BB * 256, nullptr, nullptr, 1,
                pH0, pRH0, pU, nullptr, nullptr, nullptr, nullptr, 0);
            gemm_diff2<<<dim3(32, 4, 2), 256>>>(S, pM2, pRH0, 0, pRH1, pRH2, 0);
            gemm_proj_t<<<dim3(1, 128), 256>>>(pRH0, pRH1, pRH2, wct, 128, 128,
                pGXc + (long)t * NN * BB * 128, nullptr, nullptr, 2,
                pH0, nullptr, pU, pH0,
                (l == 0) ? (pXn + (long)t * NBH) : nullptr,
                (l == 1) ? outcur : nullptr,
                (t == TT - 1) ? (fin + (long)l * BB * NN * HH) : nullptr, t);
        }
    }
}